// round 16
// baseline (speedup 1.0000x reference)
#include <cuda_runtime.h>
#include <cuda_fp16.h>
#include <math.h>
#include <stdint.h>

#define B 4
#define P 2048
#define C 512
#define D 1024
#define H 16
#define DH 64

// ---------------- scratch (static device arrays) ----------------
__device__ __half g_q[(size_t)B * H * P * DH];
__device__ __half g_k[(size_t)B * H * C * DH];
__device__ __half g_v[(size_t)B * H * C * DH];
__device__ __half g_ctx[(size_t)B * P * D];
__device__ __half g_pa[(size_t)B * P * D];
__device__ __half g_cl[(size_t)B * C * D];
__device__ __half g_wt[(size_t)3 * D * D];
__device__ __half g_ed[(size_t)B * P * C];

__device__ __forceinline__ uint32_t smem_u32(const void* p) {
    uint32_t a;
    asm("{ .reg .u64 t; cvta.to.shared.u64 t, %1; cvt.u32.u64 %0, t; }"
        : "=r"(a) : "l"(p));
    return a;
}

// ---------------- PDL helpers ----------------
__device__ __forceinline__ void gdc_wait() {
    asm volatile("griddepcontrol.wait;" ::: "memory");
}
__device__ __forceinline__ void gdc_launch_dep() {
    asm volatile("griddepcontrol.launch_dependents;" ::: "memory");
}

// ---------------- mma.sync helpers (fp16 in, fp32 accum) ----------------
__device__ __forceinline__ void ldsm_x4(uint32_t& r0, uint32_t& r1,
                                        uint32_t& r2, uint32_t& r3, uint32_t a) {
    asm volatile("ldmatrix.sync.aligned.m8n8.x4.shared.b16 {%0,%1,%2,%3}, [%4];"
                 : "=r"(r0), "=r"(r1), "=r"(r2), "=r"(r3) : "r"(a));
}
__device__ __forceinline__ void ldsm_x2t(uint32_t& r0, uint32_t& r1, uint32_t a) {
    asm volatile("ldmatrix.sync.aligned.m8n8.x2.trans.shared.b16 {%0,%1}, [%2];"
                 : "=r"(r0), "=r"(r1) : "r"(a));
}
__device__ __forceinline__ void mma16816(float* d, const uint32_t* a,
                                         const uint32_t* b) {
    asm volatile(
        "mma.sync.aligned.m16n8k16.row.col.f32.f16.f16.f32 "
        "{%0,%1,%2,%3}, {%4,%5,%6,%7}, {%8,%9}, {%0,%1,%2,%3};"
        : "+f"(d[0]), "+f"(d[1]), "+f"(d[2]), "+f"(d[3])
        : "r"(a[0]), "r"(a[1]), "r"(a[2]), "r"(a[3]), "r"(b[0]), "r"(b[1]));
}
__device__ __forceinline__ void cp16(uint32_t dst, const void* src) {
    asm volatile("cp.async.cg.shared.global [%0], [%1], 16;"
                 :: "r"(dst), "l"(src));
}
#define CP_COMMIT() asm volatile("cp.async.commit_group;" ::: "memory")
#define CP_WAIT0()  asm volatile("cp.async.wait_group 0;" ::: "memory")
#define CP_WAIT1()  asm volatile("cp.async.wait_group 1;" ::: "memory")

// pack two f32 -> f16x2 (first arg in LOW half)
__device__ __forceinline__ uint32_t pkhf(float lo, float hi) {
    uint32_t d;
    asm("cvt.rn.f16x2.f32 %0, %1, %2;" : "=r"(d) : "f"(hi), "f"(lo));
    return d;
}
__device__ __forceinline__ float exp2r(float x) {
    float y; asm("ex2.approx.ftz.f32 %0, %1;" : "=f"(y) : "f"(x)); return y;
}

// =====================================================================
// Merged prep: fp16 converts with MLP=4 | W transpose fp16.
// =====================================================================
#define CVT_CHUNK 4096
#define PA_BLKS ((B * P * D) / CVT_CHUNK)
#define CL_BLKS ((B * C * D) / CVT_CHUNK)
#define ED_BLKS ((B * P * C) / CVT_CHUNK)
#define WT_BLKS (32 * 32 * 3)
#define PREP_BLKS (PA_BLKS + CL_BLKS + ED_BLKS + WT_BLKS)

__global__ void __launch_bounds__(256) prep_all(
    const float* __restrict__ para, const float* __restrict__ cluster,
    const float* __restrict__ edge,
    const float* __restrict__ Wq, const float* __restrict__ Wk,
    const float* __restrict__ Wv,
    __half* __restrict__ pa, __half* __restrict__ cl,
    __half* __restrict__ ed, __half* __restrict__ wt)
{
    const int bid = blockIdx.x;
    if (bid < PA_BLKS + CL_BLKS + ED_BLKS) {
        const float* x;
        __half* o;
        size_t base;
        if (bid < PA_BLKS) { x = para; o = pa; base = (size_t)bid * CVT_CHUNK; }
        else if (bid < PA_BLKS + CL_BLKS) {
            x = cluster; o = cl; base = (size_t)(bid - PA_BLKS) * CVT_CHUNK;
        } else {
            x = edge; o = ed; base = (size_t)(bid - PA_BLKS - CL_BLKS) * CVT_CHUNK;
        }
        const size_t i0 = base + (size_t)threadIdx.x * 4;
        float4 v0 = *(const float4*)(x + i0);
        float4 v1 = *(const float4*)(x + i0 + 1024);
        float4 v2 = *(const float4*)(x + i0 + 2048);
        float4 v3 = *(const float4*)(x + i0 + 3072);
#define CVT_STORE(v, off)                                                      \
        do {                                                                   \
            __half2 p0{__float2half_rn((v).x), __float2half_rn((v).y)};        \
            __half2 p1{__float2half_rn((v).z), __float2half_rn((v).w)};        \
            *(__half2*)(o + i0 + (off)) = p0;                                  \
            *(__half2*)(o + i0 + (off) + 2) = p1;                              \
        } while (0)
        CVT_STORE(v0, 0);
        CVT_STORE(v1, 1024);
        CVT_STORE(v2, 2048);
        CVT_STORE(v3, 3072);
#undef CVT_STORE
        gdc_launch_dep();
        return;
    }
    __shared__ float t[32][33];
    const int wb = bid - PA_BLKS - CL_BLKS - ED_BLKS;
    const int wz = wb >> 10;
    const int rem = wb & 1023;
    const int kb = (rem & 31) * 32, nb = (rem >> 5) * 32;
    const float* W = (wz == 0) ? Wq : (wz == 1) ? Wk : Wv;
    size_t ooff = (size_t)wz * D * D;
    int tx = threadIdx.x & 31, ty = threadIdx.x >> 5;
#pragma unroll
    for (int j = 0; j < 4; j++)
        t[ty + j * 8][tx] = W[(size_t)(kb + ty + j * 8) * D + nb + tx];
    __syncthreads();
#pragma unroll
    for (int j = 0; j < 4; j++) {
        int n = nb + ty + j * 8, kk = kb + tx;
        wt[ooff + (size_t)n * D + kk] = __float2half_rn(t[tx][ty + j * 8]);
    }
    gdc_launch_dep();
}

// =====================================================================
// Projection GEMM: pure fp16 single-pass, 3-stage cp.async ring,
// warp grid 4(m) x 2(n), K chunks of 64.  (frozen + PDL)
// =====================================================================
#define PST 144
#define ARR_B (128 * PST)
#define STAGE_B (2 * ARR_B)
#define PROJ_SMEM_BYTES (3 * STAGE_B)

__global__ void __launch_bounds__(256, 2) proj_mma(
    const __half* __restrict__ pa, const __half* __restrict__ cl,
    const __half* __restrict__ wt,
    const float* __restrict__ bq, const float* __restrict__ bk,
    const float* __restrict__ bv,
    __half* __restrict__ q, __half* __restrict__ k, __half* __restrict__ v)
{
    extern __shared__ char smem[];
    const uint32_t sbase = smem_u32(smem);
    const int tid = threadIdx.x;
    const int wid = tid >> 5, lane = tid & 31;

    const int bid = blockIdx.x;
    const __half *X, *W;
    const float* bias;
    __half* o;
    int mblk, Lsh; float scale;
    if (bid < 512) {
        X = pa; W = wt;
        bias = bq; o = q; Lsh = 11;
        scale = 0.125f * 1.44269504f;
        mblk = bid >> 3;
    } else if (bid < 640) {
        X = cl; W = wt + (size_t)D * D;
        bias = bk; o = k; Lsh = 9; scale = 1.0f;
        mblk = (bid - 512) >> 3;
    } else {
        X = cl; W = wt + (size_t)2 * D * D;
        bias = bv; o = v; Lsh = 9; scale = 1.0f;
        mblk = (bid - 640) >> 3;
    }
    const int n0 = (bid & 7) * 128;
    const int m0 = mblk * 128;

    const int wm = wid >> 1, wn = wid & 1;

    auto stage_load = [&](int stg, int k0) {
        const uint32_t sb = sbase + (uint32_t)stg * STAGE_B;
        const __half* srcs[2] = {X, W};
        const int rowoff[2] = {m0, n0};
#pragma unroll
        for (int a = 0; a < 2; a++) {
            const __half* s = srcs[a];
            uint32_t ab = sb + a * ARR_B;
#pragma unroll
            for (int i = 0; i < 4; i++) {
                int idx = tid + i * 256;
                int row = idx >> 3, seg = idx & 7;
                cp16(ab + row * PST + seg * 16,
                     s + (size_t)(rowoff[a] + row) * D + k0 + seg * 8);
            }
        }
    };

    float acc[2][8][4];
#pragma unroll
    for (int i = 0; i < 2; i++)
#pragma unroll
        for (int j = 0; j < 8; j++)
#pragma unroll
            for (int qq = 0; qq < 4; qq++) acc[i][j][qq] = 0.f;

    const int a_row_in = (lane & 7) + 8 * ((lane >> 3) & 1);
    const int a_colb = (lane >> 4) * 16;
    const int b4_row = ((lane >> 4) & 1) * 8 + (lane & 7);
    const int b4_colb = ((lane >> 3) & 1) * 16;

    gdc_wait();   // prep outputs must be visible before first load

    stage_load(0, 0);
    CP_COMMIT();
    stage_load(1, 64);
    CP_COMMIT();
    CP_WAIT1();
    __syncthreads();

    for (int ck = 0; ck < 16; ck++) {
        if (ck + 2 < 16) stage_load((ck + 2) % 3, (ck + 2) * 64);
        CP_COMMIT();

        const uint32_t sb = sbase + (uint32_t)(ck % 3) * STAGE_B;
        const uint32_t xs = sb, ws = sb + ARR_B;

#pragma unroll
        for (int ks = 0; ks < 4; ks++) {
            const int kb = ks * 32;
            uint32_t bf[8][2];
#pragma unroll
            for (int pi = 0; pi < 4; pi++) {
                uint32_t boff =
                    (uint32_t)(wn * 64 + pi * 16 + b4_row) * PST + kb + b4_colb;
                ldsm_x4(bf[2 * pi][0], bf[2 * pi][1],
                        bf[2 * pi + 1][0], bf[2 * pi + 1][1], ws + boff);
            }
#pragma unroll
            for (int mi = 0; mi < 2; mi++) {
                uint32_t aoff =
                    (uint32_t)(wm * 32 + mi * 16 + a_row_in) * PST + kb + a_colb;
                uint32_t af[4];
                ldsm_x4(af[0], af[1], af[2], af[3], xs + aoff);
#pragma unroll
                for (int ni = 0; ni < 8; ni++) mma16816(acc[mi][ni], af, bf[ni]);
            }
        }
        CP_WAIT1();
        __syncthreads();
    }

    const int qr = lane >> 2;
    const int qc = (lane & 3) * 2;
    const int L = 1 << Lsh, Lm = L - 1;
#pragma unroll
    for (int mi = 0; mi < 2; mi++) {
#pragma unroll
        for (int rh = 0; rh < 2; rh++) {
            int m = m0 + wm * 32 + mi * 16 + qr + rh * 8;
            int bb = m >> Lsh, l = m & Lm;
#pragma unroll
            for (int ni = 0; ni < 8; ni++) {
                int n = n0 + wn * 64 + ni * 8 + qc;
                int hh = n >> 6, d0 = n & 63;
                float ox = (acc[mi][ni][rh * 2 + 0] + bias[n]) * scale;
                float oy = (acc[mi][ni][rh * 2 + 1] + bias[n + 1]) * scale;
                size_t off = (((size_t)bb * H + hh) * (size_t)L + l) * DH + d0;
                *(uint32_t*)(o + off) = pkhf(ox, oy);
            }
        }
    }
    gdc_launch_dep();
}

// =====================================================================
// Fused attention: pure fp16, fp16 edge, CT=64, double-buffered
// cp.async pipeline, exp2 softmax; fp16 ctx output.  (frozen + PDL)
// =====================================================================
#define AST 144
#define STG0 18432
#define STG_SZ 36864
#define ATTN_SMEM_BYTES (STG0 + 2 * STG_SZ)

__global__ void __launch_bounds__(256, 2) attn_mma(
    const __half* __restrict__ q, const __half* __restrict__ k,
    const __half* __restrict__ v,
    const __half* __restrict__ ed, __half* __restrict__ ctx)
{
    extern __shared__ char smem[];
    const uint32_t sbase = smem_u32(smem);
    const int tid = threadIdx.x;
    const int wid = tid >> 5, lane = tid & 31;
    const int b = blockIdx.z, h = blockIdx.y;
    const int p0 = blockIdx.x * 128;

    const size_t qoff = (((size_t)b * H + h) * P + p0) * DH;
    const size_t koff = (((size_t)b * H + h) * C) * DH;
    const __half* ebase = ed + ((size_t)b * P + p0) * C;

    auto load_chunk = [&](uint32_t stg, int cn) {
#pragma unroll
        for (int i = 0; i < 2; i++) {
            int idx = tid + i * 256;
            int row = idx >> 3, seg = idx & 7;
            cp16(stg + row * AST + seg * 16,
                 k + koff + (size_t)(cn + row) * DH + seg * 8);
            cp16(stg + 9216 + row * AST + seg * 16,
                 v + koff + (size_t)(cn + row) * DH + seg * 8);
        }
#pragma unroll
        for (int i = 0; i < 4; i++) {
            int idx = tid + i * 256;
            int er = idx >> 3, seg = idx & 7;
            cp16(stg + 18432 + er * AST + seg * 16,
                 ebase + (size_t)er * C + cn + seg * 8);
        }
    };

    gdc_wait();   // proj outputs must be visible before q/k/v loads

#pragma unroll
    for (int i = 0; i < 4; i++) {
        int g = tid + i * 256;
        int row = g >> 3, seg = g & 7;
        cp16(sbase + row * AST + seg * 16,
             q + qoff + (size_t)row * DH + seg * 8);
    }
    load_chunk(sbase + STG0, 0);
    CP_COMMIT();

    const int a_row = (lane & 7) + 8 * ((lane >> 3) & 1);
    const int a_colb = (lane >> 4) * 16;
    const int b4_row = ((lane >> 4) & 1) * 8 + (lane & 7);
    const int b4_colb = ((lane >> 3) & 1) * 16;
    const int r0 = lane >> 2;
    const int wr = wid * 16;
    const int c2 = (lane & 3) * 2;

    CP_WAIT0();
    __syncthreads();

    uint32_t qf[4][4];
#pragma unroll
    for (int ks = 0; ks < 4; ks++) {
        uint32_t aoff = (uint32_t)(wr + a_row) * AST + a_colb + ks * 32;
        ldsm_x4(qf[ks][0], qf[ks][1], qf[ks][2], qf[ks][3], sbase + aoff);
    }

    float m_r[2] = {-1e30f, -1e30f};
    float l_r[2] = {0.f, 0.f};
    float cacc[8][4];
#pragma unroll
    for (int i = 0; i < 8; i++)
#pragma unroll
        for (int j = 0; j < 4; j++) cacc[i][j] = 0.f;

    for (int ck = 0; ck < 8; ck++) {
        const uint32_t stgoff = STG0 + (uint32_t)(ck & 1) * STG_SZ;
        const uint32_t stg = sbase + stgoff;

        if (ck < 7) {
            load_chunk(sbase + STG0 + (uint32_t)((ck + 1) & 1) * STG_SZ,
                       (ck + 1) * 64);
            CP_COMMIT();
        }

        float s[8][4];
#pragma unroll
        for (int i = 0; i < 8; i++)
#pragma unroll
            for (int j = 0; j < 4; j++) s[i][j] = 0.f;

#pragma unroll
        for (int ks = 0; ks < 4; ks++) {
            uint32_t bf[8][2];
#pragma unroll
            for (int pi = 0; pi < 4; pi++) {
                uint32_t boff =
                    (uint32_t)(pi * 16 + b4_row) * AST + b4_colb + ks * 32;
                ldsm_x4(bf[2 * pi][0], bf[2 * pi][1],
                        bf[2 * pi + 1][0], bf[2 * pi + 1][1], stg + boff);
            }
#pragma unroll
            for (int ni = 0; ni < 8; ni++) mma16816(s[ni], qf[ks], bf[ni]);
        }

        float alpha[2];
#pragma unroll
        for (int rr = 0; rr < 2; rr++) {
            const __half* ep = (const __half*)(smem + stgoff + 18432 +
                                (size_t)(wr + r0 + rr * 8) * AST) + c2;
            float ev[8][2];
            float mx = -1e30f;
#pragma unroll
            for (int j = 0; j < 8; j++) {
                float2 e2 = __half22float2(*(const __half2*)(ep + j * 8));
                ev[j][0] = e2.x; ev[j][1] = e2.y;
                float s0 = (e2.x > 0.f) ? s[j][rr * 2] : -1e30f;
                float s1 = (e2.y > 0.f) ? s[j][rr * 2 + 1] : -1e30f;
                s[j][rr * 2] = s0; s[j][rr * 2 + 1] = s1;
                mx = fmaxf(mx, fmaxf(s0, s1));
            }
            mx = fmaxf(mx, __shfl_xor_sync(0xffffffffu, mx, 1));
            mx = fmaxf(mx, __shfl_xor_sync(0xffffffffu, mx, 2));
            float mn = fmaxf(m_r[rr], mx);
            alpha[rr] = exp2r(m_r[rr] - mn);
            m_r[rr] = mn;
            float ls = 0.f;
#pragma unroll
            for (int j = 0; j < 8; j++) {
                float ex0 = exp2r(s[j][rr * 2] - mn);
                float ex1 = exp2r(s[j][rr * 2 + 1] - mn);
                ls += ex0 + ex1;
                s[j][rr * 2] = ex0 * ev[j][0];
                s[j][rr * 2 + 1] = ex1 * ev[j][1];
            }
            ls += __shfl_xor_sync(0xffffffffu, ls, 1);
            ls += __shfl_xor_sync(0xffffffffu, ls, 2);
            l_r[rr] = l_r[rr] * alpha[rr] + ls;
        }

#pragma unroll
        for (int ni = 0; ni < 8; ni++) {
            cacc[ni][0] *= alpha[0]; cacc[ni][1] *= alpha[0];
            cacc[ni][2] *= alpha[1]; cacc[ni][3] *= alpha[1];
        }
#pragma unroll
        for (int ks = 0; ks < 4; ks++) {
            const float* t0 = s[2 * ks];
            const float* t1 = s[2 * ks + 1];
            uint32_t ap[4];
            ap[0] = pkhf(t0[0], t0[1]);
            ap[1] = pkhf(t0[2], t0[3]);
            ap[2] = pkhf(t1[0], t1[1]);
            ap[3] = pkhf(t1[2], t1[3]);
            uint32_t vrow = (uint32_t)(ks * 16 + (lane & 15)) * AST;
            uint32_t vf[8][2];
#pragma unroll
            for (int ni = 0; ni < 8; ni++)
                ldsm_x2t(vf[ni][0], vf[ni][1], stg + 9216 + vrow + ni * 16);
#pragma unroll
            for (int ni = 0; ni < 8; ni++) mma16816(cacc[ni], ap, vf[ni]);
        }

        if (ck < 7) {
            CP_WAIT0();
            __syncthreads();
        }
    }

    const float inv0 = 1.0f / l_r[0];
    const float inv1 = 1.0f / l_r[1];
    const int row0 = p0 + wr + r0;
#pragma unroll
    for (int ni = 0; ni < 8; ni++) {
        int dh = ni * 8 + c2;
        size_t base0 = ((size_t)b * P + row0) * D + h * DH + dh;
        *(uint32_t*)(ctx + base0) =
            pkhf(cacc[ni][0] * inv0, cacc[ni][1] * inv0);
        *(uint32_t*)(ctx + base0 + (size_t)8 * D) =
            pkhf(cacc[ni][2] * inv1, cacc[ni][3] * inv1);
    }
    gdc_launch_dep();
}

// =====================================================================
// LayerNorm over D=1024 from fp16 ctx: 8 rows per block, MLP=8.
// =====================================================================
__global__ void __launch_bounds__(256) ln_kernel(
    const __half* __restrict__ x, const float* __restrict__ gamma,
    const float* __restrict__ beta, float* __restrict__ out)
{
    __shared__ float rs1[8][8], rs2[8][8];
    const size_t row0 = (size_t)blockIdx.x * 8;
    const int tid = threadIdx.x;

    gdc_wait();   // attn's ctx must be visible

    uint2 raw[8];
#pragma unroll
    for (int r = 0; r < 8; r++)
        raw[r] = *(const uint2*)(x + (row0 + r) * D + tid * 4);

    float xv[8][4];
    float s1[8], s2[8];
#pragma unroll
    for (int r = 0; r < 8; r++) {
        float2 a = __half22float2(*(__half2*)&raw[r].x);
        float2 bb = __half22float2(*(__half2*)&raw[r].y);
        xv[r][0] = a.x; xv[r][1] = a.y; xv[r][2] = bb.x; xv[r][3] = bb.y;
        s1[r] = (a.x + a.y) + (bb.x + bb.y);
        s2[r] = (a.x * a.x + a.y * a.y) + (bb.x * bb.x + bb.y * bb.y);
    }
#pragma unroll
    for (int o = 16; o; o >>= 1) {
#pragma unroll
        for (int r = 0; r < 8; r++) {
            s1[r] += __shfl_xor_sync(0xffffffffu, s1[r], o);
            s2[r] += __shfl_xor_sync(0xffffffffu, s2[r], o);
        }
    }
    if ((tid & 31) == 0) {
#pragma unroll
        for (int r = 0; r < 8; r++) {
            rs1[r][tid >> 5] = s1[r];
            rs2[r][tid >> 5] = s2[r];
        }
    }
    __syncthreads();
    if (tid < 32) {
        float t1[8], t2[8];
#pragma unroll
        for (int r = 0; r < 8; r++) {
            t1[r] = (tid < 8) ? rs1[r][tid] : 0.f;
            t2[r] = (tid < 8) ? rs2[r][tid] : 0.f;
        }
#pragma unroll
        for (int o = 4; o; o >>= 1) {
#pragma unroll
            for (int r = 0; r < 8; r++) {
                t1[r] += __shfl_xor_sync(0xffffffffu, t1[r], o);
                t2[r] += __shfl_xor_sync(0xffffffffu, t2[r], o);
            }
        }
        if (tid == 0) {
#pragma unroll
            for (int r = 0; r < 8; r++) {
                rs1[r][0] = t1[r];
                rs2[r][0] = t2[r];
            }
        }
    }
    __syncthreads();
    const float4 g = *(const float4*)(gamma + tid * 4);
    const float4 bt = *(const float4*)(beta + tid * 4);
#pragma unroll
    for (int r = 0; r < 8; r++) {
        const float mu = rs1[r][0] * (1.0f / D);
        const float var = fmaxf(rs2[r][0] * (1.0f / D) - mu * mu, 0.f);
        const float rr = rsqrtf(var + 1e-6f);
        float4 o;
        o.x = (xv[r][0] - mu) * rr * g.x + bt.x;
        o.y = (xv[r][1] - mu) * rr * g.y + bt.y;
        o.z = (xv[r][2] - mu) * rr * g.z + bt.z;
        o.w = (xv[r][3] - mu) * rr * g.w + bt.w;
        *(float4*)(out + (row0 + r) * D + tid * 4) = o;
    }
}

// =====================================================================
extern "C" void kernel_launch(void* const* d_in, const int* in_sizes, int n_in,
                              void* d_out, int out_size)
{
    const float* para    = (const float*)d_in[0];
    const float* cluster = (const float*)d_in[1];
    const float* edge    = (const float*)d_in[2];
    const float* Wq = (const float*)d_in[3];
    const float* bq = (const float*)d_in[4];
    const float* Wk = (const float*)d_in[5];
    const float* bk = (const float*)d_in[6];
    const float* Wv = (const float*)d_in[7];
    const float* bv = (const float*)d_in[8];
    const float* gamma = (const float*)d_in[9];
    const float* beta  = (const float*)d_in[10];
    float* out = (float*)d_out;

    __half *cp, *qp, *kp, *vp, *pap, *clp, *wtp, *edp;
    cudaGetSymbolAddress((void**)&cp, g_ctx);
    cudaGetSymbolAddress((void**)&qp, g_q);
    cudaGetSymbolAddress((void**)&kp, g_k);
    cudaGetSymbolAddress((void**)&vp, g_v);
    cudaGetSymbolAddress((void**)&pap, g_pa);
    cudaGetSymbolAddress((void**)&clp, g_cl);
    cudaGetSymbolAddress((void**)&wtp, g_wt);
    cudaGetSymbolAddress((void**)&edp, g_ed);

    cudaFuncSetAttribute(proj_mma,
                         cudaFuncAttributeMaxDynamicSharedMemorySize,
                         PROJ_SMEM_BYTES);
    cudaFuncSetAttribute(attn_mma,
                         cudaFuncAttributeMaxDynamicSharedMemorySize,
                         ATTN_SMEM_BYTES);

    // prep (primary; no PDL attribute)
    prep_all<<<PREP_BLKS, 256>>>(para, cluster, edge, Wq, Wk, Wv,
                                 pap, clp, edp, wtp);

    // PDL launch attribute for dependent kernels
    cudaLaunchAttribute pdl;
    pdl.id = cudaLaunchAttributeProgrammaticStreamSerialization;
    pdl.val.programmaticStreamSerializationAllowed = 1;

    {
        cudaLaunchConfig_t cfg = {};
        cfg.gridDim = dim3(768, 1, 1);
        cfg.blockDim = dim3(256, 1, 1);
        cfg.dynamicSmemBytes = PROJ_SMEM_BYTES;
        cfg.stream = 0;
        cfg.attrs = &pdl;
        cfg.numAttrs = 1;
        cudaLaunchKernelEx(&cfg, proj_mma, pap, clp, wtp, bq, bk, bv,
                           qp, kp, vp);
    }
    {
        cudaLaunchConfig_t cfg = {};
        cfg.gridDim = dim3(P / 128, H, B);
        cfg.blockDim = dim3(256, 1, 1);
        cfg.dynamicSmemBytes = ATTN_SMEM_BYTES;
        cfg.stream = 0;
        cfg.attrs = &pdl;
        cfg.numAttrs = 1;
        cudaLaunchKernelEx(&cfg, attn_mma,
                           (const __half*)qp, (const __half*)kp,
                           (const __half*)vp, (const __half*)edp, cp);
    }
    {
        cudaLaunchConfig_t cfg = {};
        cfg.gridDim = dim3((B * P) / 8, 1, 1);
        cfg.blockDim = dim3(256, 1, 1);
        cfg.dynamicSmemBytes = 0;
        cfg.stream = 0;
        cfg.attrs = &pdl;
        cfg.numAttrs = 1;
        cudaLaunchKernelEx(&cfg, ln_kernel,
                           (const __half*)cp, gamma, beta, out);
    }
}

// round 17
// speedup vs baseline: 1.0013x; 1.0013x over previous
#include <cuda_runtime.h>
#include <cuda_fp16.h>
#include <math.h>
#include <stdint.h>

#define B 4
#define P 2048
#define C 512
#define D 1024
#define H 16
#define DH 64

// ---------------- scratch (static device arrays) ----------------
__device__ __half g_q[(size_t)B * H * P * DH];
__device__ __half g_k[(size_t)B * H * C * DH];
__device__ __half g_v[(size_t)B * H * C * DH];
__device__ __half g_ctx[(size_t)B * P * D];
__device__ __half g_pa[(size_t)B * P * D];
__device__ __half g_cl[(size_t)B * C * D];
__device__ __half g_wt[(size_t)3 * D * D];
__device__ __half g_ed[(size_t)B * P * C];

__device__ __forceinline__ uint32_t smem_u32(const void* p) {
    uint32_t a;
    asm("{ .reg .u64 t; cvta.to.shared.u64 t, %1; cvt.u32.u64 %0, t; }"
        : "=r"(a) : "l"(p));
    return a;
}

// ---------------- PDL helpers ----------------
__device__ __forceinline__ void gdc_wait() {
    asm volatile("griddepcontrol.wait;" ::: "memory");
}
__device__ __forceinline__ void gdc_launch_dep() {
    asm volatile("griddepcontrol.launch_dependents;" ::: "memory");
}

// ---------------- mma.sync helpers (fp16 in, fp32 accum) ----------------
__device__ __forceinline__ void ldsm_x4(uint32_t& r0, uint32_t& r1,
                                        uint32_t& r2, uint32_t& r3, uint32_t a) {
    asm volatile("ldmatrix.sync.aligned.m8n8.x4.shared.b16 {%0,%1,%2,%3}, [%4];"
                 : "=r"(r0), "=r"(r1), "=r"(r2), "=r"(r3) : "r"(a));
}
__device__ __forceinline__ void ldsm_x2t(uint32_t& r0, uint32_t& r1, uint32_t a) {
    asm volatile("ldmatrix.sync.aligned.m8n8.x2.trans.shared.b16 {%0,%1}, [%2];"
                 : "=r"(r0), "=r"(r1) : "r"(a));
}
__device__ __forceinline__ void mma16816(float* d, const uint32_t* a,
                                         const uint32_t* b) {
    asm volatile(
        "mma.sync.aligned.m16n8k16.row.col.f32.f16.f16.f32 "
        "{%0,%1,%2,%3}, {%4,%5,%6,%7}, {%8,%9}, {%0,%1,%2,%3};"
        : "+f"(d[0]), "+f"(d[1]), "+f"(d[2]), "+f"(d[3])
        : "r"(a[0]), "r"(a[1]), "r"(a[2]), "r"(a[3]), "r"(b[0]), "r"(b[1]));
}
__device__ __forceinline__ void cp16(uint32_t dst, const void* src) {
    asm volatile("cp.async.cg.shared.global [%0], [%1], 16;"
                 :: "r"(dst), "l"(src));
}
#define CP_COMMIT() asm volatile("cp.async.commit_group;" ::: "memory")
#define CP_WAIT0()  asm volatile("cp.async.wait_group 0;" ::: "memory")
#define CP_WAIT1()  asm volatile("cp.async.wait_group 1;" ::: "memory")

// pack two f32 -> f16x2 (first arg in LOW half)
__device__ __forceinline__ uint32_t pkhf(float lo, float hi) {
    uint32_t d;
    asm("cvt.rn.f16x2.f32 %0, %1, %2;" : "=r"(d) : "f"(hi), "f"(lo));
    return d;
}
__device__ __forceinline__ float exp2r(float x) {
    float y; asm("ex2.approx.ftz.f32 %0, %1;" : "=f"(y) : "f"(x)); return y;
}

// =====================================================================
// Merged prep: para/cluster fp16 convert (MLP=4) | W transpose fp16.
// (edge conversion moved into proj_mma's pre-wait window)
// =====================================================================
#define CVT_CHUNK 4096
#define PA_BLKS ((B * P * D) / CVT_CHUNK)   // 2048
#define CL_BLKS ((B * C * D) / CVT_CHUNK)   // 512
#define WT_BLKS (32 * 32 * 3)               // 3072
#define PREP_BLKS (PA_BLKS + CL_BLKS + WT_BLKS)

__global__ void __launch_bounds__(256) prep_all(
    const float* __restrict__ para, const float* __restrict__ cluster,
    const float* __restrict__ Wq, const float* __restrict__ Wk,
    const float* __restrict__ Wv,
    __half* __restrict__ pa, __half* __restrict__ cl,
    __half* __restrict__ wt)
{
    const int bid = blockIdx.x;
    if (bid < PA_BLKS + CL_BLKS) {
        const float* x;
        __half* o;
        size_t base;
        if (bid < PA_BLKS) { x = para; o = pa; base = (size_t)bid * CVT_CHUNK; }
        else { x = cluster; o = cl; base = (size_t)(bid - PA_BLKS) * CVT_CHUNK; }
        const size_t i0 = base + (size_t)threadIdx.x * 4;
        float4 v0 = *(const float4*)(x + i0);
        float4 v1 = *(const float4*)(x + i0 + 1024);
        float4 v2 = *(const float4*)(x + i0 + 2048);
        float4 v3 = *(const float4*)(x + i0 + 3072);
#define CVT_STORE(v, off)                                                      \
        do {                                                                   \
            __half2 p0{__float2half_rn((v).x), __float2half_rn((v).y)};        \
            __half2 p1{__float2half_rn((v).z), __float2half_rn((v).w)};        \
            *(__half2*)(o + i0 + (off)) = p0;                                  \
            *(__half2*)(o + i0 + (off) + 2) = p1;                              \
        } while (0)
        CVT_STORE(v0, 0);
        CVT_STORE(v1, 1024);
        CVT_STORE(v2, 2048);
        CVT_STORE(v3, 3072);
#undef CVT_STORE
        gdc_launch_dep();
        return;
    }
    __shared__ float t[32][33];
    const int wb = bid - PA_BLKS - CL_BLKS;
    const int wz = wb >> 10;
    const int rem = wb & 1023;
    const int kb = (rem & 31) * 32, nb = (rem >> 5) * 32;
    const float* W = (wz == 0) ? Wq : (wz == 1) ? Wk : Wv;
    size_t ooff = (size_t)wz * D * D;
    int tx = threadIdx.x & 31, ty = threadIdx.x >> 5;
#pragma unroll
    for (int j = 0; j < 4; j++)
        t[ty + j * 8][tx] = W[(size_t)(kb + ty + j * 8) * D + nb + tx];
    __syncthreads();
#pragma unroll
    for (int j = 0; j < 4; j++) {
        int n = nb + ty + j * 8, kk = kb + tx;
        wt[ooff + (size_t)n * D + kk] = __float2half_rn(t[tx][ty + j * 8]);
    }
    gdc_launch_dep();
}

// =====================================================================
// Projection GEMM: pure fp16 single-pass, 3-stage cp.async ring,
// warp grid 4(m) x 2(n), K chunks of 64.  Also converts edge fp32->fp16
// in the pre-gdc_wait shadow (independent of prep outputs).
// =====================================================================
#define PST 144
#define ARR_B (128 * PST)
#define STAGE_B (2 * ARR_B)
#define PROJ_SMEM_BYTES (3 * STAGE_B)
#define PROJ_GRID 768

__global__ void __launch_bounds__(256, 2) proj_mma(
    const __half* __restrict__ pa, const __half* __restrict__ cl,
    const __half* __restrict__ wt,
    const float* __restrict__ bq, const float* __restrict__ bk,
    const float* __restrict__ bv,
    const float* __restrict__ edge, __half* __restrict__ ed,
    __half* __restrict__ q, __half* __restrict__ k, __half* __restrict__ v)
{
    extern __shared__ char smem[];
    const uint32_t sbase = smem_u32(smem);
    const int tid = threadIdx.x;
    const int wid = tid >> 5, lane = tid & 31;

    // ---- edge convert (no dependency on prep; fills the PDL wait shadow)
    {
        const size_t total4 = (size_t)B * P * C / 4;   // float4 groups
        const size_t stride = (size_t)PROJ_GRID * 256;
        for (size_t i = (size_t)blockIdx.x * 256 + tid; i < total4; i += stride) {
            float4 vv = *(const float4*)(edge + i * 4);
            __half2 p0{__float2half_rn(vv.x), __float2half_rn(vv.y)};
            __half2 p1{__float2half_rn(vv.z), __float2half_rn(vv.w)};
            *(__half2*)(ed + i * 4) = p0;
            *(__half2*)(ed + i * 4 + 2) = p1;
        }
    }

    const int bid = blockIdx.x;
    const __half *X, *W;
    const float* bias;
    __half* o;
    int mblk, Lsh; float scale;
    if (bid < 512) {
        X = pa; W = wt;
        bias = bq; o = q; Lsh = 11;
        scale = 0.125f * 1.44269504f;
        mblk = bid >> 3;
    } else if (bid < 640) {
        X = cl; W = wt + (size_t)D * D;
        bias = bk; o = k; Lsh = 9; scale = 1.0f;
        mblk = (bid - 512) >> 3;
    } else {
        X = cl; W = wt + (size_t)2 * D * D;
        bias = bv; o = v; Lsh = 9; scale = 1.0f;
        mblk = (bid - 640) >> 3;
    }
    const int n0 = (bid & 7) * 128;
    const int m0 = mblk * 128;

    const int wm = wid >> 1, wn = wid & 1;

    auto stage_load = [&](int stg, int k0) {
        const uint32_t sb = sbase + (uint32_t)stg * STAGE_B;
        const __half* srcs[2] = {X, W};
        const int rowoff[2] = {m0, n0};
#pragma unroll
        for (int a = 0; a < 2; a++) {
            const __half* s = srcs[a];
            uint32_t ab = sb + a * ARR_B;
#pragma unroll
            for (int i = 0; i < 4; i++) {
                int idx = tid + i * 256;
                int row = idx >> 3, seg = idx & 7;
                cp16(ab + row * PST + seg * 16,
                     s + (size_t)(rowoff[a] + row) * D + k0 + seg * 8);
            }
        }
    };

    float acc[2][8][4];
#pragma unroll
    for (int i = 0; i < 2; i++)
#pragma unroll
        for (int j = 0; j < 8; j++)
#pragma unroll
            for (int qq = 0; qq < 4; qq++) acc[i][j][qq] = 0.f;

    const int a_row_in = (lane & 7) + 8 * ((lane >> 3) & 1);
    const int a_colb = (lane >> 4) * 16;
    const int b4_row = ((lane >> 4) & 1) * 8 + (lane & 7);
    const int b4_colb = ((lane >> 3) & 1) * 16;

    gdc_wait();   // prep outputs must be visible before first load

    stage_load(0, 0);
    CP_COMMIT();
    stage_load(1, 64);
    CP_COMMIT();
    CP_WAIT1();
    __syncthreads();

    for (int ck = 0; ck < 16; ck++) {
        if (ck + 2 < 16) stage_load((ck + 2) % 3, (ck + 2) * 64);
        CP_COMMIT();

        const uint32_t sb = sbase + (uint32_t)(ck % 3) * STAGE_B;
        const uint32_t xs = sb, ws = sb + ARR_B;

#pragma unroll
        for (int ks = 0; ks < 4; ks++) {
            const int kb = ks * 32;
            uint32_t bf[8][2];
#pragma unroll
            for (int pi = 0; pi < 4; pi++) {
                uint32_t boff =
                    (uint32_t)(wn * 64 + pi * 16 + b4_row) * PST + kb + b4_colb;
                ldsm_x4(bf[2 * pi][0], bf[2 * pi][1],
                        bf[2 * pi + 1][0], bf[2 * pi + 1][1], ws + boff);
            }
#pragma unroll
            for (int mi = 0; mi < 2; mi++) {
                uint32_t aoff =
                    (uint32_t)(wm * 32 + mi * 16 + a_row_in) * PST + kb + a_colb;
                uint32_t af[4];
                ldsm_x4(af[0], af[1], af[2], af[3], xs + aoff);
#pragma unroll
                for (int ni = 0; ni < 8; ni++) mma16816(acc[mi][ni], af, bf[ni]);
            }
        }
        CP_WAIT1();
        __syncthreads();
    }

    const int qr = lane >> 2;
    const int qc = (lane & 3) * 2;
    const int L = 1 << Lsh, Lm = L - 1;
#pragma unroll
    for (int mi = 0; mi < 2; mi++) {
#pragma unroll
        for (int rh = 0; rh < 2; rh++) {
            int m = m0 + wm * 32 + mi * 16 + qr + rh * 8;
            int bb = m >> Lsh, l = m & Lm;
#pragma unroll
            for (int ni = 0; ni < 8; ni++) {
                int n = n0 + wn * 64 + ni * 8 + qc;
                int hh = n >> 6, d0 = n & 63;
                float ox = (acc[mi][ni][rh * 2 + 0] + bias[n]) * scale;
                float oy = (acc[mi][ni][rh * 2 + 1] + bias[n + 1]) * scale;
                size_t off = (((size_t)bb * H + hh) * (size_t)L + l) * DH + d0;
                *(uint32_t*)(o + off) = pkhf(ox, oy);
            }
        }
    }
    gdc_launch_dep();
}

// =====================================================================
// Fused attention: pure fp16, fp16 edge, CT=64, double-buffered
// cp.async pipeline, exp2 softmax; fp16 ctx output.  (frozen + PDL)
// =====================================================================
#define AST 144
#define STG0 18432
#define STG_SZ 36864
#define ATTN_SMEM_BYTES (STG0 + 2 * STG_SZ)

__global__ void __launch_bounds__(256, 2) attn_mma(
    const __half* __restrict__ q, const __half* __restrict__ k,
    const __half* __restrict__ v,
    const __half* __restrict__ ed, __half* __restrict__ ctx)
{
    extern __shared__ char smem[];
    const uint32_t sbase = smem_u32(smem);
    const int tid = threadIdx.x;
    const int wid = tid >> 5, lane = tid & 31;
    const int b = blockIdx.z, h = blockIdx.y;
    const int p0 = blockIdx.x * 128;

    const size_t qoff = (((size_t)b * H + h) * P + p0) * DH;
    const size_t koff = (((size_t)b * H + h) * C) * DH;
    const __half* ebase = ed + ((size_t)b * P + p0) * C;

    auto load_chunk = [&](uint32_t stg, int cn) {
#pragma unroll
        for (int i = 0; i < 2; i++) {
            int idx = tid + i * 256;
            int row = idx >> 3, seg = idx & 7;
            cp16(stg + row * AST + seg * 16,
                 k + koff + (size_t)(cn + row) * DH + seg * 8);
            cp16(stg + 9216 + row * AST + seg * 16,
                 v + koff + (size_t)(cn + row) * DH + seg * 8);
        }
#pragma unroll
        for (int i = 0; i < 4; i++) {
            int idx = tid + i * 256;
            int er = idx >> 3, seg = idx & 7;
            cp16(stg + 18432 + er * AST + seg * 16,
                 ebase + (size_t)er * C + cn + seg * 8);
        }
    };

    gdc_wait();   // proj outputs (incl. edge fp16) must be visible

#pragma unroll
    for (int i = 0; i < 4; i++) {
        int g = tid + i * 256;
        int row = g >> 3, seg = g & 7;
        cp16(sbase + row * AST + seg * 16,
             q + qoff + (size_t)row * DH + seg * 8);
    }
    load_chunk(sbase + STG0, 0);
    CP_COMMIT();

    const int a_row = (lane & 7) + 8 * ((lane >> 3) & 1);
    const int a_colb = (lane >> 4) * 16;
    const int b4_row = ((lane >> 4) & 1) * 8 + (lane & 7);
    const int b4_colb = ((lane >> 3) & 1) * 16;
    const int r0 = lane >> 2;
    const int wr = wid * 16;
    const int c2 = (lane & 3) * 2;

    CP_WAIT0();
    __syncthreads();

    uint32_t qf[4][4];
#pragma unroll
    for (int ks = 0; ks < 4; ks++) {
        uint32_t aoff = (uint32_t)(wr + a_row) * AST + a_colb + ks * 32;
        ldsm_x4(qf[ks][0], qf[ks][1], qf[ks][2], qf[ks][3], sbase + aoff);
    }

    float m_r[2] = {-1e30f, -1e30f};
    float l_r[2] = {0.f, 0.f};
    float cacc[8][4];
#pragma unroll
    for (int i = 0; i < 8; i++)
#pragma unroll
        for (int j = 0; j < 4; j++) cacc[i][j] = 0.f;

    for (int ck = 0; ck < 8; ck++) {
        const uint32_t stgoff = STG0 + (uint32_t)(ck & 1) * STG_SZ;
        const uint32_t stg = sbase + stgoff;

        if (ck < 7) {
            load_chunk(sbase + STG0 + (uint32_t)((ck + 1) & 1) * STG_SZ,
                       (ck + 1) * 64);
            CP_COMMIT();
        }

        float s[8][4];
#pragma unroll
        for (int i = 0; i < 8; i++)
#pragma unroll
            for (int j = 0; j < 4; j++) s[i][j] = 0.f;

#pragma unroll
        for (int ks = 0; ks < 4; ks++) {
            uint32_t bf[8][2];
#pragma unroll
            for (int pi = 0; pi < 4; pi++) {
                uint32_t boff =
                    (uint32_t)(pi * 16 + b4_row) * AST + b4_colb + ks * 32;
                ldsm_x4(bf[2 * pi][0], bf[2 * pi][1],
                        bf[2 * pi + 1][0], bf[2 * pi + 1][1], stg + boff);
            }
#pragma unroll
            for (int ni = 0; ni < 8; ni++) mma16816(s[ni], qf[ks], bf[ni]);
        }

        float alpha[2];
#pragma unroll
        for (int rr = 0; rr < 2; rr++) {
            const __half* ep = (const __half*)(smem + stgoff + 18432 +
                                (size_t)(wr + r0 + rr * 8) * AST) + c2;
            float ev[8][2];
            float mx = -1e30f;
#pragma unroll
            for (int j = 0; j < 8; j++) {
                float2 e2 = __half22float2(*(const __half2*)(ep + j * 8));
                ev[j][0] = e2.x; ev[j][1] = e2.y;
                float s0 = (e2.x > 0.f) ? s[j][rr * 2] : -1e30f;
                float s1 = (e2.y > 0.f) ? s[j][rr * 2 + 1] : -1e30f;
                s[j][rr * 2] = s0; s[j][rr * 2 + 1] = s1;
                mx = fmaxf(mx, fmaxf(s0, s1));
            }
            mx = fmaxf(mx, __shfl_xor_sync(0xffffffffu, mx, 1));
            mx = fmaxf(mx, __shfl_xor_sync(0xffffffffu, mx, 2));
            float mn = fmaxf(m_r[rr], mx);
            alpha[rr] = exp2r(m_r[rr] - mn);
            m_r[rr] = mn;
            float ls = 0.f;
#pragma unroll
            for (int j = 0; j < 8; j++) {
                float ex0 = exp2r(s[j][rr * 2] - mn);
                float ex1 = exp2r(s[j][rr * 2 + 1] - mn);
                ls += ex0 + ex1;
                s[j][rr * 2] = ex0 * ev[j][0];
                s[j][rr * 2 + 1] = ex1 * ev[j][1];
            }
            ls += __shfl_xor_sync(0xffffffffu, ls, 1);
            ls += __shfl_xor_sync(0xffffffffu, ls, 2);
            l_r[rr] = l_r[rr] * alpha[rr] + ls;
        }

#pragma unroll
        for (int ni = 0; ni < 8; ni++) {
            cacc[ni][0] *= alpha[0]; cacc[ni][1] *= alpha[0];
            cacc[ni][2] *= alpha[1]; cacc[ni][3] *= alpha[1];
        }
#pragma unroll
        for (int ks = 0; ks < 4; ks++) {
            const float* t0 = s[2 * ks];
            const float* t1 = s[2 * ks + 1];
            uint32_t ap[4];
            ap[0] = pkhf(t0[0], t0[1]);
            ap[1] = pkhf(t0[2], t0[3]);
            ap[2] = pkhf(t1[0], t1[1]);
            ap[3] = pkhf(t1[2], t1[3]);
            uint32_t vrow = (uint32_t)(ks * 16 + (lane & 15)) * AST;
            uint32_t vf[8][2];
#pragma unroll
            for (int ni = 0; ni < 8; ni++)
                ldsm_x2t(vf[ni][0], vf[ni][1], stg + 9216 + vrow + ni * 16);
#pragma unroll
            for (int ni = 0; ni < 8; ni++) mma16816(cacc[ni], ap, vf[ni]);
        }

        if (ck < 7) {
            CP_WAIT0();
            __syncthreads();
        }
    }

    const float inv0 = 1.0f / l_r[0];
    const float inv1 = 1.0f / l_r[1];
    const int row0 = p0 + wr + r0;
#pragma unroll
    for (int ni = 0; ni < 8; ni++) {
        int dh = ni * 8 + c2;
        size_t base0 = ((size_t)b * P + row0) * D + h * DH + dh;
        *(uint32_t*)(ctx + base0) =
            pkhf(cacc[ni][0] * inv0, cacc[ni][1] * inv0);
        *(uint32_t*)(ctx + base0 + (size_t)8 * D) =
            pkhf(cacc[ni][2] * inv1, cacc[ni][3] * inv1);
    }
    gdc_launch_dep();
}

// =====================================================================
// LayerNorm over D=1024 from fp16 ctx: 4 rows per block (measured best).
// =====================================================================
__global__ void __launch_bounds__(256) ln_kernel(
    const __half* __restrict__ x, const float* __restrict__ gamma,
    const float* __restrict__ beta, float* __restrict__ out)
{
    __shared__ float rs1[4][8], rs2[4][8];
    const size_t row0 = (size_t)blockIdx.x * 4;
    const int tid = threadIdx.x;

    gdc_wait();   // attn's ctx must be visible

    uint2 raw[4];
#pragma unroll
    for (int r = 0; r < 4; r++)
        raw[r] = *(const uint2*)(x + (row0 + r) * D + tid * 4);

    float xv[4][4];
    float s1[4], s2[4];
#pragma unroll
    for (int r = 0; r < 4; r++) {
        float2 a = __half22float2(*(__half2*)&raw[r].x);
        float2 bb = __half22float2(*(__half2*)&raw[r].y);
        xv[r][0] = a.x; xv[r][1] = a.y; xv[r][2] = bb.x; xv[r][3] = bb.y;
        s1[r] = (a.x + a.y) + (bb.x + bb.y);
        s2[r] = (a.x * a.x + a.y * a.y) + (bb.x * bb.x + bb.y * bb.y);
    }
#pragma unroll
    for (int o = 16; o; o >>= 1) {
#pragma unroll
        for (int r = 0; r < 4; r++) {
            s1[r] += __shfl_xor_sync(0xffffffffu, s1[r], o);
            s2[r] += __shfl_xor_sync(0xffffffffu, s2[r], o);
        }
    }
    if ((tid & 31) == 0) {
#pragma unroll
        for (int r = 0; r < 4; r++) {
            rs1[r][tid >> 5] = s1[r];
            rs2[r][tid >> 5] = s2[r];
        }
    }
    __syncthreads();
    if (tid < 32) {
        float t1[4], t2[4];
#pragma unroll
        for (int r = 0; r < 4; r++) {
            t1[r] = (tid < 8) ? rs1[r][tid] : 0.f;
            t2[r] = (tid < 8) ? rs2[r][tid] : 0.f;
        }
#pragma unroll
        for (int o = 4; o; o >>= 1) {
#pragma unroll
            for (int r = 0; r < 4; r++) {
                t1[r] += __shfl_xor_sync(0xffffffffu, t1[r], o);
                t2[r] += __shfl_xor_sync(0xffffffffu, t2[r], o);
            }
        }
        if (tid == 0) {
#pragma unroll
            for (int r = 0; r < 4; r++) {
                rs1[r][0] = t1[r];
                rs2[r][0] = t2[r];
            }
        }
    }
    __syncthreads();
    const float4 g = *(const float4*)(gamma + tid * 4);
    const float4 bt = *(const float4*)(beta + tid * 4);
#pragma unroll
    for (int r = 0; r < 4; r++) {
        const float mu = rs1[r][0] * (1.0f / D);
        const float var = fmaxf(rs2[r][0] * (1.0f / D) - mu * mu, 0.f);
        const float rr = rsqrtf(var + 1e-6f);
        float4 o;
        o.x = (xv[r][0] - mu) * rr * g.x + bt.x;
        o.y = (xv[r][1] - mu) * rr * g.y + bt.y;
        o.z = (xv[r][2] - mu) * rr * g.z + bt.z;
        o.w = (xv[r][3] - mu) * rr * g.w + bt.w;
        *(float4*)(out + (row0 + r) * D + tid * 4) = o;
    }
}

// =====================================================================
extern "C" void kernel_launch(void* const* d_in, const int* in_sizes, int n_in,
                              void* d_out, int out_size)
{
    const float* para    = (const float*)d_in[0];
    const float* cluster = (const float*)d_in[1];
    const float* edge    = (const float*)d_in[2];
    const float* Wq = (const float*)d_in[3];
    const float* bq = (const float*)d_in[4];
    const float* Wk = (const float*)d_in[5];
    const float* bk = (const float*)d_in[6];
    const float* Wv = (const float*)d_in[7];
    const float* bv = (const float*)d_in[8];
    const float* gamma = (const float*)d_in[9];
    const float* beta  = (const float*)d_in[10];
    float* out = (float*)d_out;

    __half *cp, *qp, *kp, *vp, *pap, *clp, *wtp, *edp;
    cudaGetSymbolAddress((void**)&cp, g_ctx);
    cudaGetSymbolAddress((void**)&qp, g_q);
    cudaGetSymbolAddress((void**)&kp, g_k);
    cudaGetSymbolAddress((void**)&vp, g_v);
    cudaGetSymbolAddress((void**)&pap, g_pa);
    cudaGetSymbolAddress((void**)&clp, g_cl);
    cudaGetSymbolAddress((void**)&wtp, g_wt);
    cudaGetSymbolAddress((void**)&edp, g_ed);

    cudaFuncSetAttribute(proj_mma,
                         cudaFuncAttributeMaxDynamicSharedMemorySize,
                         PROJ_SMEM_BYTES);
    cudaFuncSetAttribute(attn_mma,
                         cudaFuncAttributeMaxDynamicSharedMemorySize,
                         ATTN_SMEM_BYTES);

    // prep (primary)
    prep_all<<<PREP_BLKS, 256>>>(para, cluster, Wq, Wk, Wv, pap, clp, wtp);

    cudaLaunchAttribute pdl;
    pdl.id = cudaLaunchAttributeProgrammaticStreamSerialization;
    pdl.val.programmaticStreamSerializationAllowed = 1;

    {
        cudaLaunchConfig_t cfg = {};
        cfg.gridDim = dim3(PROJ_GRID, 1, 1);
        cfg.blockDim = dim3(256, 1, 1);
        cfg.dynamicSmemBytes = PROJ_SMEM_BYTES;
        cfg.stream = 0;
        cfg.attrs = &pdl;
        cfg.numAttrs = 1;
        cudaLaunchKernelEx(&cfg, proj_mma,
                           (const __half*)pap, (const __half*)clp,
                           (const __half*)wtp, bq, bk, bv,
                           edge, edp, qp, kp, vp);
    }
    {
        cudaLaunchConfig_t cfg = {};
        cfg.gridDim = dim3(P / 128, H, B);
        cfg.blockDim = dim3(256, 1, 1);
        cfg.dynamicSmemBytes = ATTN_SMEM_BYTES;
        cfg.stream = 0;
        cfg.attrs = &pdl;
        cfg.numAttrs = 1;
        cudaLaunchKernelEx(&cfg, attn_mma,
                           (const __half*)qp, (const __half*)kp,
                           (const __half*)vp, (const __half*)edp, cp);
    }
    {
        cudaLaunchConfig_t cfg = {};
        cfg.gridDim = dim3((B * P) / 4, 1, 1);
        cfg.blockDim = dim3(256, 1, 1);
        cfg.dynamicSmemBytes = 0;
        cfg.stream = 0;
        cfg.attrs = &pdl;
        cfg.numAttrs = 1;
        cudaLaunchKernelEx(&cfg, ln_kernel,
                           (const __half*)cp, gamma, beta, out);
    }
}